// round 16
// baseline (speedup 1.0000x reference)
#include <cuda_runtime.h>

// ---------------- problem constants (fixed by setup_inputs) ----------------
#define G        64      // gt boxes per batch
#define A        5       // anchors per location
#define S        25      // score map size
#define NLOC     625     // S*S grid locations
#define NANCH    3125    // NLOC*A
#define NPAD     3128    // g_cls row stride (4-byte aligned)
#define BMAX     128
#define POS_NUM  16
#define TOTAL_NUM 64
#define THR_HIGH 0.6f
#define THR_LOW  0.3f
#define TPB      1024
#define NOFF     384     // locations offloaded to warps 20-31 (g upper half)

// ---------------- scratch (device globals) -----------------------------------
__device__ signed char g_cls[BMAX * NPAD];   // pre-truncation cls (padded rows)
__device__ int         g_pos;                // last-batch pre-trunc pos count

// ---------------- smem layout for k_iou (~78 KB, 1 block/SM) -----------------
struct SM {
    float4   xc4[G * 25];       // x-overlap shapes 0-3   [g][px]
    float    xc1[G * 25];       // x-overlap shape 4
    float4   yc4[G * 25];       // y-overlap shapes 0-3   [g][py]
    float    yc1[G * 25];       // y-overlap shape 4
    float4   sag4[G];           // area_a+area_g, shapes 0-3
    float2   sg2[G];            // {area4+area_g, gtmax-bits-or-NaN-sentinel}
    float4   gtv[G];
    float    gar[G];
    unsigned gtm[G];            // atomicMax target
    unsigned pu[A][NOFF];       // offload partial max bits
    unsigned char pa[A][NOFF];  // offload partial arg (in [32,64))
    unsigned char pk[NOFF];     // offload partial keep mask
    int      posc;
};

// Correctly-rounded fp32 divide, fast path (canonical div.rn fast sequence:
// RCP + one Newton + Markstein finish). Valid for normal operands/quotients —
// this kernel's entire domain. Used for BOTH the gtmax table and per-anchor
// IoUs -> keep-equality self-consistent.
__device__ __forceinline__ float div6(float n, float d) {
    float r;
    asm("rcp.approx.f32 %0, %1;" : "=f"(r) : "f"(d));
    r = __fmaf_rn(__fmaf_rn(-d, r, 1.0f), r, r);
    float q = __fmul_rn(n, r);
    return __fmaf_rn(__fmaf_rn(-d, q, n), r, q);
}

// ---------------- K1: fused IoU/max/arg/keep/cls/maxov/bt --------------------
// grid = B blocks of 1024. Threads 0-624 own locations; threads 640-1023
// pre-compute the g-upper-half for locations 0-383 (merged through smem).
__global__ void __launch_bounds__(TPB, 1)
k_iou(const float4* __restrict__ anchors,
      const float4* __restrict__ gt,
      float* __restrict__ out, int Bn) {
    extern __shared__ char smraw[];
    SM* s = (SM*)smraw;
    const int bA = blockIdx.x, t = threadIdx.x;

    if (t == 0) s->posc = 0;
    if (t < G) {
        float4 q = gt[bA * G + t];
        s->gtv[t] = q;
        float gw = __fadd_rn(__fsub_rn(q.z, q.x), 1.0f);
        float gh = __fadd_rn(__fsub_rn(q.w, q.y), 1.0f);
        s->gar[t] = __fmul_rn(gw, gh);
        s->gtm[t] = 0u;
    }
    __syncthreads();

    // ---- clamped 1D overlap tables (exact _rn ops, same as reference) -------
    // Separable grid: x-coords of anchor (py,px,a) equal anchors[px*5+a]'s;
    // y-coords equal anchors[py*125+a]'s.
    for (int i = t; i < G * 25; i += TPB) {
        int g = i / 25, p = i - (i / 25) * 25;
        float4 q = s->gtv[g];
        float xv[A], yv[A];
#pragma unroll
        for (int a = 0; a < A; a++) {
            float4 ax = anchors[p * 5 + a];
            float ix = __fadd_rn(__fsub_rn(fminf(ax.z, q.z), fmaxf(ax.x, q.x)), 1.0f);
            xv[a] = fmaxf(ix, 0.0f);
            float4 ay = anchors[p * 125 + a];
            float iy = __fadd_rn(__fsub_rn(fminf(ay.w, q.w), fmaxf(ay.y, q.y)), 1.0f);
            yv[a] = fmaxf(iy, 0.0f);
        }
        s->xc4[i] = make_float4(xv[0], xv[1], xv[2], xv[3]);
        s->xc1[i] = xv[4];
        s->yc4[i] = make_float4(yv[0], yv[1], yv[2], yv[3]);
        s->yc1[i] = yv[4];
    }
    __syncthreads();

    // ---- gtmax from tables (bitwise exact: fmul_rn monotone on nonneg args,
    // div monotone in I -> per-(g,shape) max-I anchor attains the max).
    if (t < G * A) {
        int g = t / A, a = t - (t / A) * A;
        float xm = 0.0f, ym = 0.0f;
        for (int p = 0; p < S; p++) {
            float xv = (a < 4) ? ((const float*)&s->xc4[g * 25 + p])[a]
                               : s->xc1[g * 25 + p];
            float yv = (a < 4) ? ((const float*)&s->yc4[g * 25 + p])[a]
                               : s->yc1[g * 25 + p];
            xm = fmaxf(xm, xv);
            ym = fmaxf(ym, yv);
        }
        float4 a4 = anchors[a];
        float aw = __fadd_rn(__fsub_rn(a4.z, a4.x), 1.0f);
        float ah = __fadd_rn(__fsub_rn(a4.w, a4.y), 1.0f);
        float I  = __fmul_rn(xm, ym);
        float v  = div6(I, __fsub_rn(__fadd_rn(__fmul_rn(aw, ah),
                                               s->gar[g]), I));
        if (I > 0.0f) atomicMax(&s->gtm[g], __float_as_uint(v));
    }
    __syncthreads();
    if (t < G) {                            // packed area+sentinel tables
        float sv[A];
#pragma unroll
        for (int a = 0; a < A; a++) {
            float4 a4 = anchors[a];
            float aw = __fadd_rn(__fsub_rn(a4.z, a4.x), 1.0f);
            float ah = __fadd_rn(__fsub_rn(a4.w, a4.y), 1.0f);
            sv[a] = __fadd_rn(__fmul_rn(aw, ah), s->gar[t]);
        }
        s->sag4[t] = make_float4(sv[0], sv[1], sv[2], sv[3]);
        unsigned gm = s->gtm[t];
        s->sg2[t] = make_float2(sv[4],
                                __uint_as_float(gm ? gm : 0xFFFFFFFFu));
    }
    __syncthreads();

    // ---- main loop ----------------------------------------------------------
    const bool owner = (t < NLOC);
    const bool offl  = (t >= 640);
    const int  loc   = owner ? t : (offl ? t - 640 : 0);
    const int  px    = loc % 25, py = loc / 25;
    const int  g0    = offl ? 32 : 0;
    const int  g1    = offl ? G : (owner ? ((t < NOFF) ? 32 : G) : 0);

    unsigned umax[A] = {0u, 0u, 0u, 0u, 0u};    // v>=0: bits monotone
    int      arg [A] = {0, 0, 0, 0, 0};
    int      keepm   = 0;

#pragma unroll 4
    for (int g = g0; g < g1; g++) {
        float4 x4 = s->xc4[g * 25 + px];
        float4 y4 = s->yc4[g * 25 + py];
        float4 sg4 = s->sag4[g];
        float2 sg2 = s->sg2[g];
        const unsigned gm = __float_as_uint(sg2.y);
        float in_[A], sa_[A];
        in_[0] = __fmul_rn(x4.x, y4.x); sa_[0] = sg4.x;
        in_[1] = __fmul_rn(x4.y, y4.y); sa_[1] = sg4.y;
        in_[2] = __fmul_rn(x4.z, y4.z); sa_[2] = sg4.z;
        in_[3] = __fmul_rn(x4.w, y4.w); sa_[3] = sg4.w;
        in_[4] = __fmul_rn(s->xc1[g * 25 + px], s->yc1[g * 25 + py]);
        sa_[4] = sg2.x;
#pragma unroll
        for (int a = 0; a < A; a++) {
            float v = div6(in_[a], __fsub_rn(sa_[a], in_[a]));
            unsigned u = __float_as_uint(v);
            if (u > umax[a]) { umax[a] = u; arg[a] = g; }  // first-idx argmax
            if (u == gm) keepm |= 1 << a;
        }
    }

    if (offl) {                                  // publish upper-half partials
        const int l2 = loc;
#pragma unroll
        for (int a = 0; a < A; a++) {
            s->pu[a][l2] = umax[a];
            s->pa[a][l2] = (unsigned char)arg[a];
        }
        s->pk[l2] = (unsigned char)keepm;
    }
    __syncthreads();
    if (t < NOFF) {                              // merge (strict >: lower g wins)
#pragma unroll
        for (int a = 0; a < A; a++) {
            unsigned u2 = s->pu[a][t];
            if (u2 > umax[a]) { umax[a] = u2; arg[a] = s->pa[a][t]; }
        }
        keepm |= s->pk[t];
    }

    int cnt = 0;
    if (owner) {
        const long movB = (long)Bn * NANCH * 6 + (long)bA * NANCH;
        const long btB  = (long)Bn * NANCH + (long)(bA * 4) * A * (S * S);
#pragma unroll
        for (int a = 0; a < A; a++) {
            const int n = loc * A + a;
            float maxv = __uint_as_float(umax[a]);
            int cls = -1;
            if (maxv >= THR_HIGH) cls = 1;
            if (maxv <= THR_LOW)  cls = 0;
            if (keepm & (1 << a)) cls = 1;
            cnt += (cls == 1);
            g_cls[(long)bA * NPAD + n] = (signed char)cls;
            out[movB + n] = maxv;

            // bt deltas (argmax gt already in registers)
            float4 a4 = anchors[n];
            float4 q  = s->gtv[arg[a]];
            float aw = a4.z - a4.x + 1.0f, ah = a4.w - a4.y + 1.0f;
            float acx = a4.x + 0.5f * aw,  acy = a4.y + 0.5f * ah;
            float gw = q.z - q.x + 1.0f,   gh = q.w - q.y + 1.0f;
            float gcx = q.x + 0.5f * gw,   gcy = q.y + 0.5f * gh;
            long o = btB + (long)a * (S * S) + loc;
            out[o]             = __fdividef(gcx - acx, aw);
            out[o + NANCH]     = __fdividef(gcy - acy, ah);
            out[o + 2 * NANCH] = __logf(__fdividef(gw, aw));
            out[o + 3 * NANCH] = __logf(__fdividef(gh, ah));
        }
    }
    if (t < NPAD - NANCH)                        // pad tail -> -1
        g_cls[(long)bA * NPAD + NANCH + t] = -1;

    // last-batch pre-truncation pos count -> g_pos (k_scan reads a scalar)
    if (bA == Bn - 1) {
#pragma unroll
        for (int off = 16; off; off >>= 1)
            cnt += __shfl_down_sync(0xffffffffu, cnt, off);
        if ((t & 31) == 0 && cnt) atomicAdd(&s->posc, cnt);
        __syncthreads();
        if (t == 0) g_pos = s->posc;
    }
}

// ---------------- K2: per-batch cumsum truncation, coalesced cls/bw ----------
__global__ void k_scan(float* __restrict__ out, int Bn) {
    __shared__ int wsum[32];
    __shared__ signed char s_cls[NANCH + 3];
    const int bA = blockIdx.x, t = threadIdx.x;
    const int lane = t & 31, w = t >> 5;

    // own chunk of 4 (one aligned 32-bit load)
    const int NI = NPAD / 4;                             // 782 ints
    int cloc[4];
    int pc = 0, nc = 0;
    if (t < NI) {
        int x = ((const int*)g_cls)[(long)bA * NI + t];
#pragma unroll
        for (int k = 0; k < 4; k++) {
            int c = (signed char)(x >> (8 * k));
            cloc[k] = c;
            pc += (c == 1);
            nc += (c == 0);
        }
    } else {
        cloc[0] = cloc[1] = cloc[2] = cloc[3] = -1;
    }

    // block-wide exclusive scan of packed (pos,neg) counts
    int v = (pc << 16) | nc;
    int inc = v;
#pragma unroll
    for (int off = 1; off < 32; off <<= 1) {
        int u = __shfl_up_sync(0xffffffffu, inc, off);
        if (lane >= off) inc += u;
    }
    if (lane == 31) wsum[w] = inc;
    __syncthreads();
    if (w == 0) {
        int x = wsum[lane];
        int xi = x;
#pragma unroll
        for (int off = 1; off < 32; off <<= 1) {
            int u = __shfl_up_sync(0xffffffffu, xi, off);
            if (lane >= off) xi += u;
        }
        wsum[lane] = xi - x;
    }
    __syncthreads();
    int exc = (inc - v) + wsum[w];
    int prun = exc >> 16;
    int nrun = exc & 0xffff;

    const int start = t * 4;
#pragma unroll
    for (int k = 0; k < 4; k++) {
        int n = start + k;
        if (n >= NANCH) break;
        int c = cloc[k];
        if (c == 1)      { prun++; if (prun > POS_NUM)   c = -1; }
        else if (c == 0) { nrun++; if (nrun > TOTAL_NUM) c = -1; }
        s_cls[n] = (signed char)c;
    }
    __syncthreads();

    const int pn = min(g_pos, POS_NUM);
    const float invp = 1.0f / (float)pn;                 // pn==0 -> inf (ref)
    const long clsB = (long)bA * NANCH;
    const long bwB  = (long)Bn * NANCH * 5 + clsB;

    for (int o = t; o < NANCH; o += 1024) {              // o = a*625+yx, coalesced
        int aa = o / (S * S), yx = o - aa * (S * S);
        int c = s_cls[yx * A + aa];                      // stride-5 LDS: no conflicts
        out[clsB + o] = (float)c;
        out[bwB + o]  = (c == 1) ? invp : 0.0f;
    }
}

// ---------------- launch ------------------------------------------------------
extern "C" void kernel_launch(void* const* d_in, const int* in_sizes, int n_in,
                              void* d_out, int out_size) {
    (void)n_in; (void)out_size;
    const float4* gt      = (const float4*)d_in[0];   // (B, G, 4)
    const float4* anchors = (const float4*)d_in[1];   // (N, 4)
    const int Bn = in_sizes[0] / (G * 4);             // 128
    float* out = (float*)d_out;

    static int smem_set = 0;
    if (!smem_set) {
        cudaFuncSetAttribute(k_iou, cudaFuncAttributeMaxDynamicSharedMemorySize,
                             (int)sizeof(SM));
        smem_set = 1;
    }
    k_iou <<<Bn, TPB, sizeof(SM)>>>(anchors, gt, out, Bn);
    k_scan<<<Bn, 1024>>>(out, Bn);
}

// round 17
// speedup vs baseline: 1.0576x; 1.0576x over previous
#include <cuda_runtime.h>

// ---------------- problem constants (fixed by setup_inputs) ----------------
#define G        64      // gt boxes per batch
#define A        5       // anchors per location
#define S        25      // score map size
#define NLOC     625     // S*S grid locations
#define NANCH    3125    // NLOC*A
#define BMAX     128
#define POS_NUM  16
#define TOTAL_NUM 64
#define THR_HIGH 0.6f
#define THR_LOW  0.3f
#define TPB      1024

// ---------------- scratch (device global) ------------------------------------
__device__ int g_pos;                // last-batch pre-trunc pos count

// ---------------- smem layout for k_iou (~71 KB, 1 block/SM) -----------------
struct SM {
    float4   xc4[G * 25];       // x-overlap shapes 0-3   [g][px]
    float    xc1[G * 25];       // x-overlap shape 4
    float4   yc4[G * 25];       // y-overlap shapes 0-3   [g][py]
    float    yc1[G * 25];       // y-overlap shape 4
    float4   sag4[G];           // area_a+area_g, shapes 0-3
    float2   sg2[G];            // {area4+area_g, gtmax-bits-or-NaN-sentinel}
    float4   gtv[G];
    float    gar[G];
    unsigned gtm[G];            // atomicMax target
    int      wsum[32];          // scan workspace
    int      tot;               // block total (pos<<16|neg)
    signed char cls[NANCH + 3]; // final truncated cls
};

// Correctly-rounded fp32 divide, fast path (canonical div.rn fast sequence:
// RCP + one Newton + Markstein finish). Valid for normal operands/quotients —
// this kernel's entire domain. Used for BOTH the gtmax table and per-anchor
// IoUs -> keep-equality self-consistent.
__device__ __forceinline__ float div6(float n, float d) {
    float r;
    asm("rcp.approx.f32 %0, %1;" : "=f"(r) : "f"(d));
    r = __fmaf_rn(__fmaf_rn(-d, r, 1.0f), r, r);
    float q = __fmul_rn(n, r);
    return __fmaf_rn(__fmaf_rn(-d, q, n), r, q);
}

// ---------------- K1: fused IoU/max/arg/keep/cls-scan/maxov/bt ---------------
// grid = B blocks of 1024 (one block = one batch image; 625 own locations).
__global__ void __launch_bounds__(TPB, 1)
k_iou(const float4* __restrict__ anchors,
      const float4* __restrict__ gt,
      float* __restrict__ out, int Bn) {
    extern __shared__ char smraw[];
    SM* s = (SM*)smraw;
    const int bA = blockIdx.x, t = threadIdx.x;
    const int lane = t & 31, w = t >> 5;

    if (t < G) {
        float4 q = gt[bA * G + t];
        s->gtv[t] = q;
        float gw = __fadd_rn(__fsub_rn(q.z, q.x), 1.0f);
        float gh = __fadd_rn(__fsub_rn(q.w, q.y), 1.0f);
        s->gar[t] = __fmul_rn(gw, gh);
        s->gtm[t] = 0u;
    }
    __syncthreads();

    // ---- clamped 1D overlap tables (exact _rn ops, same as reference) -------
    // Separable grid: x-coords of anchor (py,px,a) equal anchors[px*5+a]'s;
    // y-coords equal anchors[py*125+a]'s.
    for (int i = t; i < G * 25; i += TPB) {
        int g = i / 25, p = i - (i / 25) * 25;
        float4 q = s->gtv[g];
        float xv[A], yv[A];
#pragma unroll
        for (int a = 0; a < A; a++) {
            float4 ax = anchors[p * 5 + a];
            float ix = __fadd_rn(__fsub_rn(fminf(ax.z, q.z), fmaxf(ax.x, q.x)), 1.0f);
            xv[a] = fmaxf(ix, 0.0f);
            float4 ay = anchors[p * 125 + a];
            float iy = __fadd_rn(__fsub_rn(fminf(ay.w, q.w), fmaxf(ay.y, q.y)), 1.0f);
            yv[a] = fmaxf(iy, 0.0f);
        }
        s->xc4[i] = make_float4(xv[0], xv[1], xv[2], xv[3]);
        s->xc1[i] = xv[4];
        s->yc4[i] = make_float4(yv[0], yv[1], yv[2], yv[3]);
        s->yc1[i] = yv[4];
    }
    __syncthreads();

    // ---- gtmax from tables (bitwise exact: fmul_rn monotone on nonneg args,
    // div monotone in I -> per-(g,shape) max-I anchor attains the max).
    if (t < G * A) {
        int g = t / A, a = t - (t / A) * A;
        float xm = 0.0f, ym = 0.0f;
        for (int p = 0; p < S; p++) {
            float xv = (a < 4) ? ((const float*)&s->xc4[g * 25 + p])[a]
                               : s->xc1[g * 25 + p];
            float yv = (a < 4) ? ((const float*)&s->yc4[g * 25 + p])[a]
                               : s->yc1[g * 25 + p];
            xm = fmaxf(xm, xv);
            ym = fmaxf(ym, yv);
        }
        float4 a4 = anchors[a];
        float aw = __fadd_rn(__fsub_rn(a4.z, a4.x), 1.0f);
        float ah = __fadd_rn(__fsub_rn(a4.w, a4.y), 1.0f);
        float I  = __fmul_rn(xm, ym);
        float v  = div6(I, __fsub_rn(__fadd_rn(__fmul_rn(aw, ah),
                                               s->gar[g]), I));
        if (I > 0.0f) atomicMax(&s->gtm[g], __float_as_uint(v));
    }
    __syncthreads();
    if (t < G) {                            // packed area+sentinel tables
        float sv[A];
#pragma unroll
        for (int a = 0; a < A; a++) {
            float4 a4 = anchors[a];
            float aw = __fadd_rn(__fsub_rn(a4.z, a4.x), 1.0f);
            float ah = __fadd_rn(__fsub_rn(a4.w, a4.y), 1.0f);
            sv[a] = __fadd_rn(__fmul_rn(aw, ah), s->gar[t]);
        }
        s->sag4[t] = make_float4(sv[0], sv[1], sv[2], sv[3]);
        unsigned gm = s->gtm[t];
        s->sg2[t] = make_float2(sv[4],
                                __uint_as_float(gm ? gm : 0xFFFFFFFFu));
    }
    __syncthreads();

    // ---- main loop: thread t = location t (t < 625) -------------------------
    const bool owner = (t < NLOC);
    const int  loc = owner ? t : 0;
    const int  px = loc % 25, py = loc / 25;

    unsigned umax[A] = {0u, 0u, 0u, 0u, 0u};    // v>=0: bits monotone
    int      arg [A] = {0, 0, 0, 0, 0};
    int      keepm   = 0;

    if (owner) {
#pragma unroll 4
        for (int g = 0; g < G; g++) {
            float4 x4  = s->xc4[g * 25 + px];
            float4 y4  = s->yc4[g * 25 + py];
            float4 sg4 = s->sag4[g];
            float2 sg2 = s->sg2[g];
            const unsigned gm = __float_as_uint(sg2.y);
            float in_[A], sa_[A];
            in_[0] = __fmul_rn(x4.x, y4.x); sa_[0] = sg4.x;
            in_[1] = __fmul_rn(x4.y, y4.y); sa_[1] = sg4.y;
            in_[2] = __fmul_rn(x4.z, y4.z); sa_[2] = sg4.z;
            in_[3] = __fmul_rn(x4.w, y4.w); sa_[3] = sg4.w;
            in_[4] = __fmul_rn(s->xc1[g * 25 + px], s->yc1[g * 25 + py]);
            sa_[4] = sg2.x;
#pragma unroll
            for (int a = 0; a < A; a++) {
                float v = div6(in_[a], __fsub_rn(sa_[a], in_[a]));
                unsigned u = __float_as_uint(v);
                if (u > umax[a]) { umax[a] = u; arg[a] = g; }  // first-idx max
                if (u == gm) keepm |= 1 << a;
            }
        }
    }

    // ---- pre-truncation cls + maxov + bt writes -----------------------------
    int cl[A];
    int pc = 0, nc = 0;
    if (owner) {
        const long movB = (long)Bn * NANCH * 6 + (long)bA * NANCH;
        const long btB  = (long)Bn * NANCH + (long)(bA * 4) * A * (S * S);
#pragma unroll
        for (int a = 0; a < A; a++) {
            const int n = loc * A + a;
            float maxv = __uint_as_float(umax[a]);
            int c = -1;
            if (maxv >= THR_HIGH) c = 1;
            if (maxv <= THR_LOW)  c = 0;
            if (keepm & (1 << a)) c = 1;
            cl[a] = c;
            pc += (c == 1);
            nc += (c == 0);
            out[movB + n] = maxv;

            // bt deltas (argmax gt already in registers)
            float4 a4 = anchors[n];
            float4 q  = s->gtv[arg[a]];
            float aw = a4.z - a4.x + 1.0f, ah = a4.w - a4.y + 1.0f;
            float acx = a4.x + 0.5f * aw,  acy = a4.y + 0.5f * ah;
            float gw = q.z - q.x + 1.0f,   gh = q.w - q.y + 1.0f;
            float gcx = q.x + 0.5f * gw,   gcy = q.y + 0.5f * gh;
            long o = btB + (long)a * (S * S) + loc;
            out[o]             = __fdividef(gcx - acx, aw);
            out[o + NANCH]     = __fdividef(gcy - acy, ah);
            out[o + 2 * NANCH] = __logf(__fdividef(gw, aw));
            out[o + 3 * NANCH] = __logf(__fdividef(gh, ah));
        }
    }

    // ---- block-wide exclusive scan of packed (pos,neg) counts ---------------
    // thread t owns anchors [5t, 5t+5): scan order == anchor order.
    const int v = (pc << 16) | nc;
    int inc = v;
#pragma unroll
    for (int off = 1; off < 32; off <<= 1) {
        int u = __shfl_up_sync(0xffffffffu, inc, off);
        if (lane >= off) inc += u;
    }
    if (lane == 31) s->wsum[w] = inc;
    __syncthreads();
    if (w == 0) {
        int x = s->wsum[lane];
        int xi = x;
#pragma unroll
        for (int off = 1; off < 32; off <<= 1) {
            int u = __shfl_up_sync(0xffffffffu, xi, off);
            if (lane >= off) xi += u;
        }
        s->wsum[lane] = xi - x;            // exclusive warp offsets
        if (lane == 31) s->tot = xi;       // block totals
    }
    __syncthreads();

    if (owner) {
        int exc = (inc - v) + s->wsum[w];
        int prun = exc >> 16;
        int nrun = exc & 0xffff;
#pragma unroll
        for (int a = 0; a < A; a++) {
            int c = cl[a];
            if (c == 1)      { prun++; if (prun > POS_NUM)   c = -1; }
            else if (c == 0) { nrun++; if (nrun > TOTAL_NUM) c = -1; }
            s->cls[loc * A + a] = (signed char)c;
        }
    }
    if (bA == Bn - 1 && t == 0) g_pos = s->tot >> 16;   // last-batch pos count
    __syncthreads();

    // ---- coalesced cls write (output order o = a*625 + yx) ------------------
    const long clsB = (long)bA * NANCH;
    for (int o = t; o < NANCH; o += TPB) {
        int aa = o / (S * S), yx = o - aa * (S * S);
        out[clsB + o] = (float)s->cls[yx * A + aa];
    }
}

// ---------------- K2: bw from written cls + last-batch pos scalar ------------
__global__ void k_bw(float* __restrict__ out, int Bn) {
    const int bA = blockIdx.x, t = threadIdx.x;
    const int pn = min(g_pos, POS_NUM);
    const float invp = 1.0f / (float)pn;                 // pn==0 -> inf (ref)
    const long clsB = (long)bA * NANCH;
    const long bwB  = (long)Bn * NANCH * 5 + clsB;
    for (int o = t; o < NANCH; o += TPB) {
        float c = out[clsB + o];
        out[bwB + o] = (c == 1.0f) ? invp : 0.0f;
    }
}

// ---------------- launch ------------------------------------------------------
extern "C" void kernel_launch(void* const* d_in, const int* in_sizes, int n_in,
                              void* d_out, int out_size) {
    (void)n_in; (void)out_size;
    const float4* gt      = (const float4*)d_in[0];   // (B, G, 4)
    const float4* anchors = (const float4*)d_in[1];   // (N, 4)
    const int Bn = in_sizes[0] / (G * 4);             // 128
    float* out = (float*)d_out;

    static int smem_set = 0;
    if (!smem_set) {
        cudaFuncSetAttribute(k_iou, cudaFuncAttributeMaxDynamicSharedMemorySize,
                             (int)sizeof(SM));
        smem_set = 1;
    }
    k_iou<<<Bn, TPB, sizeof(SM)>>>(anchors, gt, out, Bn);
    k_bw <<<Bn, TPB>>>(out, Bn);
}